// round 1
// baseline (speedup 1.0000x reference)
#include <cuda_runtime.h>
#include <cstdint>

#define WS        7
#define NTOK      49
#define CH        64
#define CQ        8
#define HWDIM     224
#define XS_STRIDE 68     // pad: 4t+c bank pattern -> conflict-free, 16B-aligned rows
#define QK_STRIDE 9      // odd stride -> conflict-free along tokens
#define ATT_STRIDE 51    // gcd(51,32)=1 -> conflict-free softmax row access
#define NTHREADS  128

// Dynamic smem layout (floats), each segment rounded to 4 floats for float4 alignment
#define OFF_XS   0
#define SZ_XS    (NTOK * XS_STRIDE)        // 3332
#define OFF_WVT  (OFF_XS + SZ_XS)          // 3332
#define SZ_WVT   (CH * CH)                 // 4096
#define OFF_WQT  (OFF_WVT + SZ_WVT)        // 7428
#define SZ_WQT   (CH * CQ)                 // 512
#define OFF_WKT  (OFF_WQT + SZ_WQT)        // 7940
#define SZ_WKT   (CH * CQ)                 // 512
#define OFF_QS   (OFF_WKT + SZ_WKT)        // 8452
#define SZ_QS    444                       // 49*9=441 -> 444
#define OFF_KS   (OFF_QS + SZ_QS)          // 8896
#define SZ_KS    444
#define OFF_ATT  (OFF_KS + SZ_KS)          // 9340
#define SZ_ATT   2500                      // 49*51=2499 -> 2500
#define OFF_VS   (OFF_ATT + SZ_ATT)        // 11840 (mult of 4 -> float4 OK)
#define SZ_VS    (NTOK * CH)               // 3136
#define SMEM_FLOATS (OFF_VS + SZ_VS)       // 14976
#define SMEM_BYTES  (SMEM_FLOATS * 4)      // 59904

__global__ void __launch_bounds__(NTHREADS)
lattn_kernel(const float* __restrict__ x,
             const float* __restrict__ Wq, const float* __restrict__ bq,
             const float* __restrict__ Wk, const float* __restrict__ bk,
             const float* __restrict__ Wv, const float* __restrict__ bv,
             const float* __restrict__ gamma,
             float* __restrict__ out)
{
    extern __shared__ float sm[];
    float* xs  = sm + OFF_XS;    // [49][68]  x window (later holds final output)
    float* wvt = sm + OFF_WVT;   // [64][64]  Wv transposed: wvt[c][o]
    float* wqt = sm + OFF_WQT;   // [64][8]
    float* wkt = sm + OFF_WKT;   // [64][8]
    float* qs  = sm + OFF_QS;    // [49][9]
    float* ks  = sm + OFF_KS;    // [49][9]
    float* att = sm + OFF_ATT;   // [49][51]
    float* vs  = sm + OFF_VS;    // [49][64]

    const int tid = threadIdx.x;
    const int blk = blockIdx.x;
    const int b  = blk >> 10;          // blk / 1024
    const int l  = blk & 1023;
    const int wh = l >> 5, ww = l & 31;
    const int h0 = wh * WS, w0 = ww * WS;

    const float* xb = x + (size_t)b * CH * HWDIM * HWDIM;

    // ---- Phase 0: load x window (lane-contiguous in w for coalescing) + weights
    #pragma unroll
    for (int idx = tid; idx < CH * NTOK; idx += NTHREADS) {
        int c = idx / NTOK;
        int t = idx - c * NTOK;
        int ph = t / WS, pw = t - ph * WS;
        xs[t * XS_STRIDE + c] = __ldg(&xb[((size_t)c * HWDIM + (h0 + ph)) * HWDIM + (w0 + pw)]);
    }
    for (int idx = tid; idx < CH * CH; idx += NTHREADS) {
        int o = idx >> 6, c = idx & 63;
        wvt[c * CH + o] = __ldg(&Wv[idx]);
    }
    for (int idx = tid; idx < CQ * CH; idx += NTHREADS) {
        int o = idx >> 6, c = idx & 63;
        wqt[c * CQ + o] = __ldg(&Wq[idx]);
        wkt[c * CQ + o] = __ldg(&Wk[idx]);
    }
    __syncthreads();

    // ---- Phase 1a: V projection, register tile 7 tokens x 4 out-channels (112 threads)
    if (tid < 112) {
        const int og = tid & 15, tg = tid >> 4;
        const int o0 = og * 4, t0 = tg * WS;
        float acc[7][4];
        #pragma unroll
        for (int i = 0; i < 7; i++)
            #pragma unroll
            for (int j = 0; j < 4; j++) acc[i][j] = 0.0f;

        #pragma unroll 4
        for (int c = 0; c < CH; c++) {
            float4 w = *reinterpret_cast<const float4*>(wvt + c * CH + o0);
            #pragma unroll
            for (int i = 0; i < 7; i++) {
                float xv = xs[(t0 + i) * XS_STRIDE + c];
                acc[i][0] = fmaf(xv, w.x, acc[i][0]);
                acc[i][1] = fmaf(xv, w.y, acc[i][1]);
                acc[i][2] = fmaf(xv, w.z, acc[i][2]);
                acc[i][3] = fmaf(xv, w.w, acc[i][3]);
            }
        }
        float b0 = __ldg(&bv[o0 + 0]), b1 = __ldg(&bv[o0 + 1]);
        float b2 = __ldg(&bv[o0 + 2]), b3 = __ldg(&bv[o0 + 3]);
        #pragma unroll
        for (int i = 0; i < 7; i++) {
            float4 r;
            r.x = acc[i][0] + b0; r.y = acc[i][1] + b1;
            r.z = acc[i][2] + b2; r.w = acc[i][3] + b3;
            *reinterpret_cast<float4*>(vs + (t0 + i) * CH + o0) = r;
        }
    }

    // ---- Phase 1b: Q and K projections (784 small dots, all 128 threads)
    for (int idx = tid; idx < 2 * NTOK * CQ; idx += NTHREADS) {
        int which = (idx >= NTOK * CQ);
        int r = which ? (idx - NTOK * CQ) : idx;
        int t = r >> 3, o = r & 7;
        const float* wt = which ? wkt : wqt;
        const float* xr = xs + t * XS_STRIDE;
        float s = 0.0f;
        #pragma unroll 8
        for (int c = 0; c < CH; c++) s = fmaf(xr[c], wt[c * CQ + o], s);
        s += which ? __ldg(&bk[o]) : __ldg(&bq[o]);
        (which ? ks : qs)[t * QK_STRIDE + o] = s;
    }
    __syncthreads();

    // ---- Phase 2: logits  att[n][m] = <q_n, k_m>  (dim 8)
    for (int idx = tid; idx < NTOK * NTOK; idx += NTHREADS) {
        int n = idx / NTOK;
        int m = idx - n * NTOK;
        const float* qr = qs + n * QK_STRIDE;
        const float* kr = ks + m * QK_STRIDE;
        float s = 0.0f;
        #pragma unroll
        for (int c = 0; c < CQ; c++) s = fmaf(qr[c], kr[c], s);
        att[n * ATT_STRIDE + m] = s;
    }
    __syncthreads();

    // ---- Phase 3: softmax over keys (one thread per row)
    if (tid < NTOK) {
        float* row = att + tid * ATT_STRIDE;
        float mx = row[0];
        #pragma unroll 7
        for (int m = 1; m < NTOK; m++) mx = fmaxf(mx, row[m]);
        float s = 0.0f;
        #pragma unroll 7
        for (int m = 0; m < NTOK; m++) {
            float e = __expf(row[m] - mx);
            row[m] = e;
            s += e;
        }
        float rinv = 1.0f / s;
        #pragma unroll 7
        for (int m = 0; m < NTOK; m++) row[m] *= rinv;
    }
    __syncthreads();

    // ---- Phase 4: out = att @ V, fused residual into xs (in place)
    const float g = __ldg(gamma);
    if (tid < 112) {
        const int og = tid & 15, tg = tid >> 4;
        const int c0 = og * 4, n0 = tg * WS;
        float acc[7][4];
        #pragma unroll
        for (int i = 0; i < 7; i++)
            #pragma unroll
            for (int j = 0; j < 4; j++) acc[i][j] = 0.0f;

        #pragma unroll 4
        for (int m = 0; m < NTOK; m++) {
            float4 vv = *reinterpret_cast<const float4*>(vs + m * CH + c0);
            #pragma unroll
            for (int i = 0; i < 7; i++) {
                float a = att[(n0 + i) * ATT_STRIDE + m];
                acc[i][0] = fmaf(a, vv.x, acc[i][0]);
                acc[i][1] = fmaf(a, vv.y, acc[i][1]);
                acc[i][2] = fmaf(a, vv.z, acc[i][2]);
                acc[i][3] = fmaf(a, vv.w, acc[i][3]);
            }
        }
        #pragma unroll
        for (int i = 0; i < 7; i++) {
            float* xr = xs + (n0 + i) * XS_STRIDE + c0;
            float4 xv = *reinterpret_cast<const float4*>(xr);
            xv.x = fmaf(g, acc[i][0], xv.x);
            xv.y = fmaf(g, acc[i][1], xv.y);
            xv.z = fmaf(g, acc[i][2], xv.z);
            xv.w = fmaf(g, acc[i][3], xv.w);
            *reinterpret_cast<float4*>(xr) = xv;
        }
    }
    __syncthreads();

    // ---- Phase 5: coalesced-ish store (lane-contiguous in w; L2 merges partial sectors)
    float* ob = out + (size_t)b * CH * HWDIM * HWDIM;
    #pragma unroll
    for (int idx = tid; idx < CH * NTOK; idx += NTHREADS) {
        int c = idx / NTOK;
        int t = idx - c * NTOK;
        int ph = t / WS, pw = t - ph * WS;
        ob[((size_t)c * HWDIM + (h0 + ph)) * HWDIM + (w0 + pw)] = xs[t * XS_STRIDE + c];
    }
}

extern "C" void kernel_launch(void* const* d_in, const int* in_sizes, int n_in,
                              void* d_out, int out_size)
{
    const float* x     = (const float*)d_in[0];
    const float* Wq    = (const float*)d_in[1];
    const float* bq    = (const float*)d_in[2];
    const float* Wk    = (const float*)d_in[3];
    const float* bk    = (const float*)d_in[4];
    const float* Wv    = (const float*)d_in[5];
    const float* bv    = (const float*)d_in[6];
    const float* gamma = (const float*)d_in[7];
    float* out = (float*)d_out;

    cudaFuncSetAttribute(lattn_kernel, cudaFuncAttributeMaxDynamicSharedMemorySize, SMEM_BYTES);

    const int B = 16;
    const int nwin = (HWDIM / WS) * (HWDIM / WS);  // 1024
    dim3 grid(B * nwin);
    lattn_kernel<<<grid, NTHREADS, SMEM_BYTES>>>(x, Wq, bq, Wk, bk, Wv, bv, gamma, out);
}